// round 2
// baseline (speedup 1.0000x reference)
#include <cuda_runtime.h>

#define DD    512     // in_dim == out_dim
#define ROWS  4096    // B * N
#define NOBJ  128     // N (neighbors per row)
#define NLAB  16
#define BM    128
#define BN    128
#define BK    32
#define TM    8
#define TN    8

// Scratch (allocation-free rule: __device__ globals)
__device__ float g_Wsum[DD * DD];        // 1 MB: weights[0] + weights[1], [o][i]
__device__ float g_counts[ROWS * NLAB];  // 256 KB: per-row label histogram (float)
__device__ int   g_is64;                 // graph dtype flag

// ---------------------------------------------------------------------------
// Detect whether graph buffer is int64 (odd int32 slots all zero) or int32.
// Labels are in [0,16), so for int64 every high word is 0. Sampling 8192 odd
// int32 slots distinguishes the two layouts deterministically for this input.
// ---------------------------------------------------------------------------
__global__ void detect_kernel(const int* __restrict__ g32) {
    __shared__ int any;
    if (threadIdx.x == 0) any = 0;
    __syncthreads();
    int local = 0;
    for (int i = threadIdx.x; i < 8192; i += blockDim.x)
        local |= g32[2 * i + 1];     // max index 16383 < 524288, safe for both dtypes
    if (local) atomicOr(&any, 1);
    __syncthreads();
    if (threadIdx.x == 0) g_is64 = (any == 0) ? 1 : 0;
}

// ---------------------------------------------------------------------------
// Wsum[o][i] = w[0][o][i] + w[1][o][i]
// ---------------------------------------------------------------------------
__global__ void prep_wsum_kernel(const float* __restrict__ w) {
    int idx = blockIdx.x * blockDim.x + threadIdx.x;
    if (idx < DD * DD) g_Wsum[idx] = w[idx] + w[DD * DD + idx];
}

// ---------------------------------------------------------------------------
// Per-row histogram of graph labels -> g_counts[row][label] as float.
// 4 rows per block (128 threads, one warp per row), smem atomics.
// ---------------------------------------------------------------------------
__global__ void hist_kernel(const void* __restrict__ graph) {
    __shared__ int c[4][NLAB];
    const int tid  = threadIdx.x;
    const int sub  = tid >> 5;            // warp id 0..3 -> row within block
    const int lane = tid & 31;
    const int row  = blockIdx.x * 4 + sub;
    if (lane < NLAB) c[sub][lane] = 0;
    __syncthreads();
    const int is64 = g_is64;
    #pragma unroll
    for (int q = 0; q < 4; q++) {
        int col = lane + 32 * q;
        int lab;
        if (is64) lab = (int)((const long long*)graph)[(long long)row * NOBJ + col];
        else      lab = ((const int*)graph)[row * NOBJ + col];
        atomicAdd(&c[sub][lab & (NLAB - 1)], 1);
    }
    __syncthreads();
    if (lane < NLAB) g_counts[row * NLAB + lane] = (float)c[sub][lane];
}

// ---------------------------------------------------------------------------
// Fused: out = feat + feat @ Wsum^T + counts @ bias
// Classic 128x128x32 SGEMM tile, 256 threads, 8x8 per thread, plus a rank-16
// extension (counts x bias) and epilogue add of feat.
// Static smem = 16K + 16K + 8K + 8K = 48 KB exactly.
// ---------------------------------------------------------------------------
__global__ __launch_bounds__(256) void gemm_fused_kernel(
    const float* __restrict__ feat,   // [4096, 512]
    const float* __restrict__ bias,   // [16, 512]
    float* __restrict__ out)          // [4096, 512]
{
    __shared__ float As[BK][BM];
    __shared__ float Bs[BK][BN];
    __shared__ float biasS[NLAB][BN];
    __shared__ float cF[NLAB][BM];

    const int tid = threadIdx.x;
    const int m0 = blockIdx.y * BM;
    const int n0 = blockIdx.x * BN;
    const int tx = tid & 15;          // 16 col-groups of 8
    const int ty = tid >> 4;          // 16 row-groups of 8

    float acc[TM][TN];
    #pragma unroll
    for (int i = 0; i < TM; i++)
        #pragma unroll
        for (int j = 0; j < TN; j++) acc[i][j] = 0.f;

    // Stage bias tile and counts tile (consumed after the main loop; the
    // first __syncthreads below orders these writes).
    for (int i = tid; i < NLAB * BN; i += 256) {
        int l = i >> 7, j = i & 127;
        biasS[l][j] = bias[l * DD + n0 + j];
    }
    for (int i = tid; i < BM * NLAB; i += 256) {
        int r = i >> 4, l = i & 15;
        cF[l][r] = g_counts[(m0 + r) * NLAB + l];
    }

    for (int k0 = 0; k0 < DD; k0 += BK) {
        // Load 128x32 A and B tiles as float4, store transposed [k][m]
        #pragma unroll
        for (int q = 0; q < 4; q++) {
            int f = tid + 256 * q;
            int r = f >> 3;
            int kk = (f & 7) << 2;
            float4 va = *(const float4*)(feat   + (size_t)(m0 + r) * DD + k0 + kk);
            As[kk + 0][r] = va.x; As[kk + 1][r] = va.y;
            As[kk + 2][r] = va.z; As[kk + 3][r] = va.w;
            float4 vb = *(const float4*)(g_Wsum + (size_t)(n0 + r) * DD + k0 + kk);
            Bs[kk + 0][r] = vb.x; Bs[kk + 1][r] = vb.y;
            Bs[kk + 2][r] = vb.z; Bs[kk + 3][r] = vb.w;
        }
        __syncthreads();

        #pragma unroll
        for (int k = 0; k < BK; k++) {
            float ra[TM], rb[TN];
            *(float4*)&ra[0] = *(const float4*)&As[k][ty * TM];
            *(float4*)&ra[4] = *(const float4*)&As[k][ty * TM + 4];
            *(float4*)&rb[0] = *(const float4*)&Bs[k][tx * TN];
            *(float4*)&rb[4] = *(const float4*)&Bs[k][tx * TN + 4];
            #pragma unroll
            for (int i = 0; i < TM; i++)
                #pragma unroll
                for (int j = 0; j < TN; j++)
                    acc[i][j] = fmaf(ra[i], rb[j], acc[i][j]);
        }
        __syncthreads();
    }

    // Rank-16 extension: acc += counts[m][l] * bias[l][n]
    #pragma unroll
    for (int l = 0; l < NLAB; l++) {
        float ra[TM], rb[TN];
        #pragma unroll
        for (int i = 0; i < TM; i++) ra[i] = cF[l][ty * TM + i];
        #pragma unroll
        for (int j = 0; j < TN; j++) rb[j] = biasS[l][tx * TN + j];
        #pragma unroll
        for (int i = 0; i < TM; i++)
            #pragma unroll
            for (int j = 0; j < TN; j++)
                acc[i][j] = fmaf(ra[i], rb[j], acc[i][j]);
    }

    // Epilogue: += feat (identity term), write out (float4)
    #pragma unroll
    for (int i = 0; i < TM; i++) {
        size_t base = (size_t)(m0 + ty * TM + i) * DD + n0 + tx * TN;
        float4 f0 = *(const float4*)(feat + base);
        float4 f1 = *(const float4*)(feat + base + 4);
        float4 o0 = make_float4(acc[i][0] + f0.x, acc[i][1] + f0.y,
                                acc[i][2] + f0.z, acc[i][3] + f0.w);
        float4 o1 = make_float4(acc[i][4] + f1.x, acc[i][5] + f1.y,
                                acc[i][6] + f1.z, acc[i][7] + f1.w);
        *(float4*)(out + base)     = o0;
        *(float4*)(out + base + 4) = o1;
    }
}

extern "C" void kernel_launch(void* const* d_in, const int* in_sizes, int n_in,
                              void* d_out, int out_size) {
    const float* feat  = (const float*)d_in[0];
    const void*  graph = d_in[1];
    const float* w     = (const float*)d_in[2];
    const float* bias  = (const float*)d_in[3];
    float* out = (float*)d_out;

    detect_kernel<<<1, 256>>>((const int*)graph);
    prep_wsum_kernel<<<(DD * DD + 255) / 256, 256>>>(w);
    hist_kernel<<<ROWS / 4, 128>>>(graph);
    dim3 grid(DD / BN, ROWS / BM);
    gemm_fused_kernel<<<grid, 256>>>(feat, bias, out);
}

// round 6
// speedup vs baseline: 3.2901x; 3.2901x over previous
#include <cuda_runtime.h>
#include <cuda_fp16.h>
#include <cstdint>

#define DD    512
#define ROWS  4096
#define NLAB  16
#define KTOT  544            // 512 feat + 16 counts/bias + 16 zero pad
#define NSTG  17             // K stages of 32 halves
#define BK    32             // halves per stage
#define STRD  40             // smem row stride in halves (80B, conflict-free, 16B-mult)

// ---------------- device-global scratch (allocation-free rule) -------------
__device__ __align__(16) __half g_A[ROWS * KTOT];   // 4.5 MB
__device__ __align__(16) __half g_B[DD * KTOT];     // 0.56 MB

// ---------------------------------------------------------------------------
// prepA: g_A[r][0:512] = half(feat[r]); [512+l] = count of label l in graph
// row r; [528:544] = 0.  int64-vs-int32 layout probed per block (labels<16 =>
// odd int32 slots all zero iff int64; 128 probes).
// ---------------------------------------------------------------------------
__global__ __launch_bounds__(128) void prepA_kernel(const float* __restrict__ feat,
                                                    const int* __restrict__ g32) {
    __shared__ int c[NLAB];
    __shared__ int anyOdd;
    const int r = blockIdx.x, t = threadIdx.x;
    if (t < NLAB) c[t] = 0;
    if (t == 0) anyOdd = 0;
    __syncthreads();
    if (g32[2048 * t + 1]) atomicOr(&anyOdd, 1);   // max idx 260097 < 524288
    float4 v = *(const float4*)(feat + (size_t)r * DD + t * 4);
    __syncthreads();
    const int is64 = (anyOdd == 0);
    const int idx = r * 128 + t;
    const int lab = g32[is64 ? 2 * idx : idx] & (NLAB - 1);
    atomicAdd(&c[lab], 1);
    __half2 h0 = __floats2half2_rn(v.x, v.y);
    __half2 h1 = __floats2half2_rn(v.z, v.w);
    uint2 pack;
    pack.x = *(uint32_t*)&h0;
    pack.y = *(uint32_t*)&h1;
    *(uint2*)(g_A + (size_t)r * KTOT + t * 4) = pack;
    __syncthreads();
    if (t < NLAB)          g_A[(size_t)r * KTOT + DD + t] = __float2half_rn((float)c[t]);
    else if (t < 2 * NLAB) g_A[(size_t)r * KTOT + DD + t] = __float2half_rn(0.f);
}

// ---------------------------------------------------------------------------
// prepB: g_B[o][k] = half(w0[o][k]+w1[o][k]) k<512; half(bias[k-512][o]) for
// 512<=k<528; 0 else.  B is K-major: D[m][n] = sum_k A[m][k]*B[n][k].
// ---------------------------------------------------------------------------
__global__ void prepB_kernel(const float* __restrict__ w, const float* __restrict__ bias) {
    const int o = blockIdx.x, k = threadIdx.x;   // 512 blocks x 544 threads
    float v;
    if (k < DD)             v = w[o * DD + k] + w[DD * DD + o * DD + k];
    else if (k < DD + NLAB) v = bias[(k - DD) * DD + o];
    else                    v = 0.f;
    g_B[(size_t)o * KTOT + k] = __float2half_rn(v);
}

// ============================ mma GEMM =====================================
__device__ __forceinline__ uint32_t smem_u32(const void* p) {
    uint32_t a;
    asm("{ .reg .u64 t; cvta.to.shared.u64 t, %1; cvt.u32.u64 %0, t; }" : "=r"(a) : "l"(p));
    return a;
}
#define CP_ASYNC16(dst, src) \
    asm volatile("cp.async.cg.shared.global [%0], [%1], 16;" :: "r"(dst), "l"(src) : "memory")
#define CP_COMMIT() asm volatile("cp.async.commit_group;" ::: "memory")
#define CP_WAIT(n)  asm volatile("cp.async.wait_group %0;" :: "n"(n) : "memory")
#define LDM_X4(r0, r1, r2, r3, addr) \
    asm volatile("ldmatrix.sync.aligned.m8n8.x4.shared.b16 {%0,%1,%2,%3}, [%4];" \
        : "=r"(r0), "=r"(r1), "=r"(r2), "=r"(r3) : "r"(addr))
#define MMA16816(c, a, b) \
    asm volatile("mma.sync.aligned.m16n8k16.row.col.f32.f16.f16.f32 " \
        "{%0,%1,%2,%3}, {%4,%5,%6,%7}, {%8,%9}, {%0,%1,%2,%3};" \
        : "+f"((c)[0]), "+f"((c)[1]), "+f"((c)[2]), "+f"((c)[3]) \
        : "r"((a)[0]), "r"((a)[1]), "r"((a)[2]), "r"((a)[3]), "r"((b)[0]), "r"((b)[1]))

// out[m][n] = sum_k A[m][k]*B[n][k] + feat[m][n]
// 128x128 block, 8 warps (2x4), warp tile 64x32, BK=32 halves, cp.async x2-buf
// B tile is [n][k] K-major => NON-trans ldmatrix yields the mma B fragment
// (lane i: n=i/4, k=2*(i%4)+{0,1}) directly.
__global__ __launch_bounds__(256) void gemm_mma_kernel(const float* __restrict__ feat,
                                                       float* __restrict__ out) {
    __shared__ __align__(16) __half sA[2][128 * STRD];
    __shared__ __align__(16) __half sB[2][128 * STRD];

    const int tid = threadIdx.x, wid = tid >> 5, lane = tid & 31;
    const int g = lane >> 2, tg = lane & 3;
    const int wm0 = (wid >> 2) * 64;          // warp row origin in tile
    const int wn0 = (wid & 3) * 32;           // warp col origin in tile
    const int m0 = blockIdx.y * 128, n0 = blockIdx.x * 128;

    const uint32_t aB[2] = { smem_u32(&sA[0][0]), smem_u32(&sA[1][0]) };
    const uint32_t bB[2] = { smem_u32(&sB[0][0]), smem_u32(&sB[1][0]) };

    float c[4][4][4];
    #pragma unroll
    for (int i = 0; i < 4; i++)
        #pragma unroll
        for (int j = 0; j < 4; j++)
            #pragma unroll
            for (int q = 0; q < 4; q++) c[i][j][q] = 0.f;

    // ---- stage loader: 128 rows x 32 halves (4 chunks of 8 halves) each tile
    auto load_stage = [&](int s, int buf) {
        #pragma unroll
        for (int q = 0; q < 2; q++) {
            int id = tid + 256 * q;           // 512 chunks for A
            int row = id >> 2, kc = id & 3;
            uint32_t dst = aB[buf] + (row * STRD + kc * 8) * 2;
            const __half* src = g_A + (size_t)(m0 + row) * KTOT + s * BK + kc * 8;
            CP_ASYNC16(dst, src);
        }
        #pragma unroll
        for (int q = 0; q < 2; q++) {
            int id = tid + 256 * q;
            int row = id >> 2, kc = id & 3;
            uint32_t dst = bB[buf] + (row * STRD + kc * 8) * 2;
            const __half* src = g_B + (size_t)(n0 + row) * KTOT + s * BK + kc * 8;
            CP_ASYNC16(dst, src);
        }
    };

    load_stage(0, 0); CP_COMMIT();
    load_stage(1, 1); CP_COMMIT();
    CP_WAIT(1);
    __syncthreads();

    const int lrow = lane & 15, lcol8 = (lane >> 4) << 3;

    for (int s = 0; s < NSTG; s++) {
        const int buf = s & 1;
        #pragma unroll
        for (int ks = 0; ks < 2; ks++) {      // two k16 steps per stage
            uint32_t a[4][4], b[4][2];
            #pragma unroll
            for (int mi = 0; mi < 4; mi++) {
                uint32_t addr = aB[buf] +
                    ((wm0 + mi * 16 + lrow) * STRD + ks * 16 + lcol8) * 2;
                LDM_X4(a[mi][0], a[mi][1], a[mi][2], a[mi][3], addr);
            }
            #pragma unroll
            for (int nb = 0; nb < 2; nb++) {  // each x4 covers 2 n-frags (16 n)
                uint32_t t0, t1, t2, t3;
                uint32_t addr = bB[buf] +
                    ((wn0 + nb * 16 + lrow) * STRD + ks * 16 + lcol8) * 2;
                LDM_X4(t0, t1, t2, t3, addr);
                // t0=(n0-7,k0-7) t1=(n8-15,k0-7) t2=(n0-7,k8-15) t3=(n8-15,k8-15)
                b[2 * nb][0] = t0; b[2 * nb + 1][0] = t1;
                b[2 * nb][1] = t2; b[2 * nb + 1][1] = t3;
            }
            #pragma unroll
            for (int mi = 0; mi < 4; mi++)
                #pragma unroll
                for (int nj = 0; nj < 4; nj++)
                    MMA16816(c[mi][nj], a[mi], b[nj]);
        }
        __syncthreads();                       // everyone done reading buf
        if (s + 2 < NSTG) { load_stage(s + 2, buf); CP_COMMIT(); }
        if (s + 1 < NSTG) {
            if (s + 2 < NSTG) { CP_WAIT(1); } else { CP_WAIT(0); }
            __syncthreads();                   // next buf ready
        }
    }

    // ---- epilogue: += feat, fp32 out
    #pragma unroll
    for (int mi = 0; mi < 4; mi++) {
        const int row0 = m0 + wm0 + mi * 16 + g;
        const int row1 = row0 + 8;
        #pragma unroll
        for (int nj = 0; nj < 4; nj++) {
            const int col = n0 + wn0 + nj * 8 + tg * 2;
            float2 f0 = *(const float2*)(feat + (size_t)row0 * DD + col);
            float2 f1 = *(const float2*)(feat + (size_t)row1 * DD + col);
            float2 o0 = make_float2(c[mi][nj][0] + f0.x, c[mi][nj][1] + f0.y);
            float2 o1 = make_float2(c[mi][nj][2] + f1.x, c[mi][nj][3] + f1.y);
            *(float2*)(out + (size_t)row0 * DD + col) = o0;
            *(float2*)(out + (size_t)row1 * DD + col) = o1;
        }
    }
}

// ================================ host =====================================
extern "C" void kernel_launch(void* const* d_in, const int* in_sizes, int n_in,
                              void* d_out, int out_size) {
    const float* feat = (const float*)d_in[0];
    const int*   g32  = (const int*)d_in[1];
    const float* w    = (const float*)d_in[2];
    const float* bias = (const float*)d_in[3];
    float* out = (float*)d_out;

    prepA_kernel<<<ROWS, 128>>>(feat, g32);
    prepB_kernel<<<DD, KTOT>>>(w, bias);
    dim3 grid(DD / 128, ROWS / 128);   // (4, 32) = 128 CTAs
    gemm_mma_kernel<<<grid, 256>>>(feat, out);
}

// round 7
// speedup vs baseline: 3.6170x; 1.0993x over previous
#include <cuda_runtime.h>
#include <cuda_fp16.h>
#include <cstdint>

#define DD    512
#define ROWS  4096
#define NLAB  16
#define KTOT  544            // 512 feat + 16 counts/bias + 16 zero pad
#define NSTG  17             // K stages of 32 halves
#define BK    32             // halves per stage
#define STRD  40             // smem row stride in halves (80B, conflict-free, 16B-mult)
#define NBUF  4              // cp.async ring depth

// ---------------- device-global scratch (allocation-free rule) -------------
__device__ __align__(16) __half g_A[ROWS * KTOT];   // 4.5 MB
__device__ __align__(16) __half g_B[DD * KTOT];     // 0.56 MB
__device__ int g_is64;

// ---------------------------------------------------------------------------
// prepB: g_B[o][k] = half(w0[o][k]+w1[o][k]) k<512; half(bias[k-512][o]) for
// 512<=k<528; 0 else.  Block 0 additionally runs the int64-vs-int32 probe
// ONCE (labels<16 => odd int32 slots all zero iff int64; 128 probes).
// ---------------------------------------------------------------------------
__global__ void prepB_kernel(const float* __restrict__ w, const float* __restrict__ bias,
                             const int* __restrict__ g32) {
    const int o = blockIdx.x, k = threadIdx.x;   // 512 blocks x 544 threads
    if (o == 0) {
        __shared__ int anyOdd;
        if (k == 0) anyOdd = 0;
        __syncthreads();
        if (k < 128 && g32[2048 * k + 1]) atomicOr(&anyOdd, 1);  // max idx 260097 < 524288
        __syncthreads();
        if (k == 0) g_is64 = (anyOdd == 0);
    }
    float v;
    if (k < DD)             v = w[o * DD + k] + w[DD * DD + o * DD + k];
    else if (k < DD + NLAB) v = bias[(k - DD) * DD + o];
    else                    v = 0.f;
    g_B[(size_t)o * KTOT + k] = __float2half_rn(v);
}

// ---------------------------------------------------------------------------
// prepA: 2048 blocks x 128 threads, 2 rows per block.
//   g_A[r][0:512]   = half(feat[r][:])   (8 halves/thread, 16B stores)
//   g_A[r][512+l]   = label-l count of graph row r
//   g_A[r][528:544] = 0
// ---------------------------------------------------------------------------
__global__ __launch_bounds__(128) void prepA_kernel(const float* __restrict__ feat,
                                                    const void* __restrict__ graph) {
    __shared__ int c[2][NLAB];
    const int t = threadIdx.x;
    const int rl = t >> 6;                  // row within block (0/1)
    const int r  = blockIdx.x * 2 + rl;
    const int colg = (t & 63) * 8;
    if (t < 2 * NLAB) c[t >> 4][t & 15] = 0;
    __syncthreads();

    // feat -> half (8 values)
    const float4* fp = (const float4*)(feat + (size_t)r * DD + colg);
    float4 v0 = fp[0], v1 = fp[1];
    __half2 h0 = __floats2half2_rn(v0.x, v0.y);
    __half2 h1 = __floats2half2_rn(v0.z, v0.w);
    __half2 h2 = __floats2half2_rn(v1.x, v1.y);
    __half2 h3 = __floats2half2_rn(v1.z, v1.w);
    uint4 pk;
    pk.x = *(uint32_t*)&h0; pk.y = *(uint32_t*)&h1;
    pk.z = *(uint32_t*)&h2; pk.w = *(uint32_t*)&h3;
    *(uint4*)(g_A + (size_t)r * KTOT + colg) = pk;

    // two labels per thread, 16B/8B coalesced
    int l0, l1;
    const int pair = r * 64 + (t & 63);     // pair index within graph rows
    if (g_is64) {
        longlong2 q = ((const longlong2*)graph)[pair];
        l0 = (int)q.x; l1 = (int)q.y;
    } else {
        int2 q = ((const int2*)graph)[pair];
        l0 = q.x; l1 = q.y;
    }
    atomicAdd(&c[rl][l0 & (NLAB - 1)], 1);
    atomicAdd(&c[rl][l1 & (NLAB - 1)], 1);
    __syncthreads();

    if (t < 32) {
        int rr = t >> 4, l = t & 15;
        g_A[(size_t)(blockIdx.x * 2 + rr) * KTOT + DD + l] =
            __float2half_rn((float)c[rr][l]);
    } else if (t < 64) {
        int u = t - 32;
        int rr = u >> 4, l = u & 15;
        g_A[(size_t)(blockIdx.x * 2 + rr) * KTOT + DD + NLAB + l] = __float2half_rn(0.f);
    }
}

// ============================ mma GEMM =====================================
__device__ __forceinline__ uint32_t smem_u32(const void* p) {
    uint32_t a;
    asm("{ .reg .u64 t; cvta.to.shared.u64 t, %1; cvt.u32.u64 %0, t; }" : "=r"(a) : "l"(p));
    return a;
}
#define CP_ASYNC16(dst, src) \
    asm volatile("cp.async.cg.shared.global [%0], [%1], 16;" :: "r"(dst), "l"(src) : "memory")
#define CP_COMMIT() asm volatile("cp.async.commit_group;" ::: "memory")
#define CP_WAIT(n)  asm volatile("cp.async.wait_group %0;" :: "n"(n) : "memory")
#define LDM_X4(r0, r1, r2, r3, addr) \
    asm volatile("ldmatrix.sync.aligned.m8n8.x4.shared.b16 {%0,%1,%2,%3}, [%4];" \
        : "=r"(r0), "=r"(r1), "=r"(r2), "=r"(r3) : "r"(addr))
#define MMA16816(c, a, b) \
    asm volatile("mma.sync.aligned.m16n8k16.row.col.f32.f16.f16.f32 " \
        "{%0,%1,%2,%3}, {%4,%5,%6,%7}, {%8,%9}, {%0,%1,%2,%3};" \
        : "+f"((c)[0]), "+f"((c)[1]), "+f"((c)[2]), "+f"((c)[3]) \
        : "r"((a)[0]), "r"((a)[1]), "r"((a)[2]), "r"((a)[3]), "r"((b)[0]), "r"((b)[1]))

// out[m][n] = sum_k A[m][k]*B[n][k] + feat[m][n]
// 128x128 block, 8 warps (2x4), warp tile 64x32, BK=32 halves, 4-stage ring.
// B tile is [n][k] K-major => NON-trans ldmatrix yields the mma B fragment.
__global__ __launch_bounds__(256) void gemm_mma_kernel(const float* __restrict__ feat,
                                                       float* __restrict__ out) {
    extern __shared__ __align__(16) __half smem[];
    __half* sA = smem;                        // NBUF x 128*STRD
    __half* sB = smem + NBUF * 128 * STRD;    // NBUF x 128*STRD

    const int tid = threadIdx.x, wid = tid >> 5, lane = tid & 31;
    const int g = lane >> 2, tg = lane & 3;
    const int wm0 = (wid >> 2) * 64;          // warp row origin in tile
    const int wn0 = (wid & 3) * 32;           // warp col origin in tile
    const int m0 = blockIdx.y * 128, n0 = blockIdx.x * 128;

    const uint32_t aBase = smem_u32(sA);
    const uint32_t bBase = smem_u32(sB);

    float c[4][4][4];
    #pragma unroll
    for (int i = 0; i < 4; i++)
        #pragma unroll
        for (int j = 0; j < 4; j++)
            #pragma unroll
            for (int q = 0; q < 4; q++) c[i][j][q] = 0.f;

    auto load_stage = [&](int s, int buf) {
        const uint32_t aD = aBase + buf * (128 * STRD * 2);
        const uint32_t bD = bBase + buf * (128 * STRD * 2);
        #pragma unroll
        for (int q = 0; q < 2; q++) {
            int id = tid + 256 * q;           // 512 chunks of 8 halves
            int row = id >> 2, kc = id & 3;
            CP_ASYNC16(aD + (row * STRD + kc * 8) * 2,
                       g_A + (size_t)(m0 + row) * KTOT + s * BK + kc * 8);
        }
        #pragma unroll
        for (int q = 0; q < 2; q++) {
            int id = tid + 256 * q;
            int row = id >> 2, kc = id & 3;
            CP_ASYNC16(bD + (row * STRD + kc * 8) * 2,
                       g_B + (size_t)(n0 + row) * KTOT + s * BK + kc * 8);
        }
    };

    #pragma unroll
    for (int i = 0; i < NBUF - 1; i++) { load_stage(i, i); CP_COMMIT(); }

    const int lrow = lane & 15, lcol8 = (lane >> 4) << 3;

    for (int s = 0; s < NSTG; s++) {
        const int buf = s & (NBUF - 1);
        CP_WAIT(NBUF - 2);                    // stage s resident
        __syncthreads();                      // publish; also fences buf reuse
        const uint32_t aT = aBase + buf * (128 * STRD * 2);
        const uint32_t bT = bBase + buf * (128 * STRD * 2);
        #pragma unroll
        for (int ks = 0; ks < 2; ks++) {      // two k16 steps per stage
            uint32_t a[4][4], b[4][2];
            #pragma unroll
            for (int mi = 0; mi < 4; mi++) {
                uint32_t addr = aT + ((wm0 + mi * 16 + lrow) * STRD + ks * 16 + lcol8) * 2;
                LDM_X4(a[mi][0], a[mi][1], a[mi][2], a[mi][3], addr);
            }
            #pragma unroll
            for (int nb = 0; nb < 2; nb++) {  // each x4 covers 2 n-frags (16 n)
                uint32_t t0, t1, t2, t3;
                uint32_t addr = bT + ((wn0 + nb * 16 + lrow) * STRD + ks * 16 + lcol8) * 2;
                LDM_X4(t0, t1, t2, t3, addr);
                b[2 * nb][0] = t0; b[2 * nb + 1][0] = t1;
                b[2 * nb][1] = t2; b[2 * nb + 1][1] = t3;
            }
            #pragma unroll
            for (int mi = 0; mi < 4; mi++)
                #pragma unroll
                for (int nj = 0; nj < 4; nj++)
                    MMA16816(c[mi][nj], a[mi], b[nj]);
        }
        const int nxt = s + NBUF - 1;
        if (nxt < NSTG) load_stage(nxt, nxt & (NBUF - 1));
        CP_COMMIT();                          // empty group in tail keeps accounting
    }

    // ---- epilogue: += feat, fp32 out
    #pragma unroll
    for (int mi = 0; mi < 4; mi++) {
        const int row0 = m0 + wm0 + mi * 16 + g;
        const int row1 = row0 + 8;
        #pragma unroll
        for (int nj = 0; nj < 4; nj++) {
            const int col = n0 + wn0 + nj * 8 + tg * 2;
            float2 f0 = *(const float2*)(feat + (size_t)row0 * DD + col);
            float2 f1 = *(const float2*)(feat + (size_t)row1 * DD + col);
            float2 o0 = make_float2(c[mi][nj][0] + f0.x, c[mi][nj][1] + f0.y);
            float2 o1 = make_float2(c[mi][nj][2] + f1.x, c[mi][nj][3] + f1.y);
            *(float2*)(out + (size_t)row0 * DD + col) = o0;
            *(float2*)(out + (size_t)row1 * DD + col) = o1;
        }
    }
}

// ================================ host =====================================
#define GEMM_SMEM (NBUF * 2 * 128 * STRD * 2)   // 81920 B

extern "C" void kernel_launch(void* const* d_in, const int* in_sizes, int n_in,
                              void* d_out, int out_size) {
    const float* feat = (const float*)d_in[0];
    const int*   g32  = (const int*)d_in[1];
    const float* w    = (const float*)d_in[2];
    const float* bias = (const float*)d_in[3];
    float* out = (float*)d_out;

    static bool attr_set = false;
    if (!attr_set) {
        cudaFuncSetAttribute(gemm_mma_kernel,
                             cudaFuncAttributeMaxDynamicSharedMemorySize, GEMM_SMEM);
        attr_set = true;
    }

    prepB_kernel<<<DD, KTOT>>>(w, bias, g32);       // also runs dtype probe once
    prepA_kernel<<<ROWS / 2, 128>>>(feat, g32);
    dim3 grid(DD / 128, ROWS / 128);                // (4, 32) = 128 CTAs
    gemm_mma_kernel<<<grid, 256, GEMM_SMEM>>>(feat, out);
}

// round 9
// speedup vs baseline: 3.8377x; 1.0610x over previous
#include <cuda_runtime.h>
#include <cuda_fp16.h>
#include <cstdint>

#define DD    512
#define ROWS  4096
#define NLAB  16
#define KTOT  544            // 512 feat + 16 counts/bias + 16 zero pad
#define NSTG  17             // K stages of 32 halves
#define BK    32             // halves per stage
#define STRD  40             // smem row stride in halves (80B, conflict-free, 16B-mult)
#define NBUF  4              // cp.async ring depth

// ---------------- device-global scratch (allocation-free rule) -------------
__device__ __align__(16) __half g_A[ROWS * KTOT];   // 4.5 MB
__device__ __align__(16) __half g_B[DD * KTOT];     // 0.56 MB
__device__ int g_is64;

// ---------------------------------------------------------------------------
// prepB: g_B[o][k] = half(w0[o][k]+w1[o][k]) k<512; half(bias[k-512][o]) for
// 512<=k<528; 0 else.  512 blocks x 128 threads:
//   t<64   : 8 k-elements each via 2 float4 loads -> one uint4 half store
//   64-95  : one tail element each (k = 512 + t-64)
// Block 0 additionally runs the int64-vs-int32 probe ONCE.
// ---------------------------------------------------------------------------
__global__ __launch_bounds__(128) void prepB_kernel(const float* __restrict__ w,
                                                    const float* __restrict__ bias,
                                                    const int* __restrict__ g32) {
    const int o = blockIdx.x, t = threadIdx.x;
    if (o == 0) {
        __shared__ int anyOdd;
        if (t == 0) anyOdd = 0;
        __syncthreads();
        if (g32[2048 * t + 1]) atomicOr(&anyOdd, 1);   // max idx 260097 < 524288
        __syncthreads();
        if (t == 0) g_is64 = (anyOdd == 0);
    }
    if (t < 64) {
        const int k = t * 8;
        const float4* p0 = (const float4*)(w + (size_t)o * DD + k);
        const float4* p1 = (const float4*)(w + (size_t)DD * DD + (size_t)o * DD + k);
        float4 a0 = p0[0], a1 = p0[1], b0 = p1[0], b1 = p1[1];
        __half2 h0 = __floats2half2_rn(a0.x + b0.x, a0.y + b0.y);
        __half2 h1 = __floats2half2_rn(a0.z + b0.z, a0.w + b0.w);
        __half2 h2 = __floats2half2_rn(a1.x + b1.x, a1.y + b1.y);
        __half2 h3 = __floats2half2_rn(a1.z + b1.z, a1.w + b1.w);
        uint4 pk;
        pk.x = *(uint32_t*)&h0; pk.y = *(uint32_t*)&h1;
        pk.z = *(uint32_t*)&h2; pk.w = *(uint32_t*)&h3;
        *(uint4*)(g_B + (size_t)o * KTOT + k) = pk;
    } else if (t < 96) {
        const int u = t - 64;                 // 0..31 -> k = 512+u
        float v = (u < NLAB) ? bias[u * DD + o] : 0.f;
        g_B[(size_t)o * KTOT + DD + u] = __float2half_rn(v);
    }
}

// ---------------------------------------------------------------------------
// prepA: 2048 blocks x 128 threads, 2 rows per block.
//   g_A[r][0:512]   = half(feat[r][:])   (8 halves/thread, 16B stores)
//   g_A[r][512+l]   = label-l count of graph row r;  [528:544] = 0
// ---------------------------------------------------------------------------
__global__ __launch_bounds__(128) void prepA_kernel(const float* __restrict__ feat,
                                                    const void* __restrict__ graph) {
    __shared__ int c[2][NLAB];
    const int t = threadIdx.x;
    const int rl = t >> 6;                  // row within block (0/1)
    const int r  = blockIdx.x * 2 + rl;
    const int colg = (t & 63) * 8;
    if (t < 2 * NLAB) c[t >> 4][t & 15] = 0;
    __syncthreads();

    const float4* fp = (const float4*)(feat + (size_t)r * DD + colg);
    float4 v0 = fp[0], v1 = fp[1];
    __half2 h0 = __floats2half2_rn(v0.x, v0.y);
    __half2 h1 = __floats2half2_rn(v0.z, v0.w);
    __half2 h2 = __floats2half2_rn(v1.x, v1.y);
    __half2 h3 = __floats2half2_rn(v1.z, v1.w);
    uint4 pk;
    pk.x = *(uint32_t*)&h0; pk.y = *(uint32_t*)&h1;
    pk.z = *(uint32_t*)&h2; pk.w = *(uint32_t*)&h3;
    *(uint4*)(g_A + (size_t)r * KTOT + colg) = pk;

    int l0, l1;
    const int pair = r * 64 + (t & 63);
    if (g_is64) {
        longlong2 q = ((const longlong2*)graph)[pair];
        l0 = (int)q.x; l1 = (int)q.y;
    } else {
        int2 q = ((const int2*)graph)[pair];
        l0 = q.x; l1 = q.y;
    }
    atomicAdd(&c[rl][l0 & (NLAB - 1)], 1);
    atomicAdd(&c[rl][l1 & (NLAB - 1)], 1);
    __syncthreads();

    if (t < 32) {
        int rr = t >> 4, l = t & 15;
        g_A[(size_t)(blockIdx.x * 2 + rr) * KTOT + DD + l] =
            __float2half_rn((float)c[rr][l]);
    } else if (t < 64) {
        int u = t - 32;
        int rr = u >> 4, l = u & 15;
        g_A[(size_t)(blockIdx.x * 2 + rr) * KTOT + DD + NLAB + l] = __float2half_rn(0.f);
    }
}

// ============================ mma GEMM =====================================
__device__ __forceinline__ uint32_t smem_u32(const void* p) {
    uint32_t a;
    asm("{ .reg .u64 t; cvta.to.shared.u64 t, %1; cvt.u32.u64 %0, t; }" : "=r"(a) : "l"(p));
    return a;
}
#define CP_ASYNC16(dst, src) \
    asm volatile("cp.async.cg.shared.global [%0], [%1], 16;" :: "r"(dst), "l"(src) : "memory")
#define CP_COMMIT() asm volatile("cp.async.commit_group;" ::: "memory")
#define CP_WAIT(n)  asm volatile("cp.async.wait_group %0;" :: "n"(n) : "memory")
#define LDM_X4(r0, r1, r2, r3, addr) \
    asm volatile("ldmatrix.sync.aligned.m8n8.x4.shared.b16 {%0,%1,%2,%3}, [%4];" \
        : "=r"(r0), "=r"(r1), "=r"(r2), "=r"(r3) : "r"(addr))
#define MMA16816(c, a, b) \
    asm volatile("mma.sync.aligned.m16n8k16.row.col.f32.f16.f16.f32 " \
        "{%0,%1,%2,%3}, {%4,%5,%6,%7}, {%8,%9}, {%0,%1,%2,%3};" \
        : "+f"((c)[0]), "+f"((c)[1]), "+f"((c)[2]), "+f"((c)[3]) \
        : "r"((a)[0]), "r"((a)[1]), "r"((a)[2]), "r"((a)[3]), "r"((b)[0]), "r"((b)[1]))

// out[m][n] = sum_k A[m][k]*B[n][k] + feat[m][n]
// 128x128 CTA tile, 512 threads = 16 warps (4x4), warp tile 32x32, 4-deep ring.
// B tile is [n][k] K-major => NON-trans ldmatrix yields the mma B fragment.
__global__ __launch_bounds__(512) void gemm_mma_kernel(const float* __restrict__ feat,
                                                       float* __restrict__ out) {
    extern __shared__ __align__(16) __half smem[];
    __half* sA = smem;                        // NBUF x 128*STRD
    __half* sB = smem + NBUF * 128 * STRD;    // NBUF x 128*STRD

    const int tid = threadIdx.x, wid = tid >> 5, lane = tid & 31;
    const int g = lane >> 2, tg = lane & 3;
    const int wm0 = (wid >> 2) * 32;          // warp row origin in tile
    const int wn0 = (wid & 3) * 32;           // warp col origin in tile
    const int m0 = blockIdx.y * 128, n0 = blockIdx.x * 128;

    const uint32_t aBase = smem_u32(sA);
    const uint32_t bBase = smem_u32(sB);

    float c[2][4][4];
    #pragma unroll
    for (int i = 0; i < 2; i++)
        #pragma unroll
        for (int j = 0; j < 4; j++)
            #pragma unroll
            for (int q = 0; q < 4; q++) c[i][j][q] = 0.f;

    auto load_stage = [&](int s, int buf) {
        const uint32_t aD = aBase + buf * (128 * STRD * 2);
        const uint32_t bD = bBase + buf * (128 * STRD * 2);
        const int row = tid >> 2, kc = tid & 3;      // 512 chunks of 8 halves
        CP_ASYNC16(aD + (row * STRD + kc * 8) * 2,
                   g_A + (size_t)(m0 + row) * KTOT + s * BK + kc * 8);
        CP_ASYNC16(bD + (row * STRD + kc * 8) * 2,
                   g_B + (size_t)(n0 + row) * KTOT + s * BK + kc * 8);
    };

    #pragma unroll
    for (int i = 0; i < NBUF - 1; i++) { load_stage(i, i); CP_COMMIT(); }

    const int lrow = lane & 15, lcol8 = (lane >> 4) << 3;

    for (int s = 0; s < NSTG; s++) {
        const int buf = s & (NBUF - 1);
        CP_WAIT(NBUF - 2);                    // stage s resident
        __syncthreads();                      // publish; also fences buf reuse
        const uint32_t aT = aBase + buf * (128 * STRD * 2);
        const uint32_t bT = bBase + buf * (128 * STRD * 2);
        #pragma unroll
        for (int ks = 0; ks < 2; ks++) {      // two k16 steps per stage
            uint32_t a[2][4], b[4][2];
            #pragma unroll
            for (int mi = 0; mi < 2; mi++) {
                uint32_t addr = aT + ((wm0 + mi * 16 + lrow) * STRD + ks * 16 + lcol8) * 2;
                LDM_X4(a[mi][0], a[mi][1], a[mi][2], a[mi][3], addr);
            }
            #pragma unroll
            for (int nb = 0; nb < 2; nb++) {  // each x4 covers 2 n-frags (16 n)
                uint32_t t0, t1, t2, t3;
                uint32_t addr = bT + ((wn0 + nb * 16 + lrow) * STRD + ks * 16 + lcol8) * 2;
                LDM_X4(t0, t1, t2, t3, addr);
                b[2 * nb][0] = t0; b[2 * nb + 1][0] = t1;
                b[2 * nb][1] = t2; b[2 * nb + 1][1] = t3;
            }
            #pragma unroll
            for (int mi = 0; mi < 2; mi++)
                #pragma unroll
                for (int nj = 0; nj < 4; nj++)
                    MMA16816(c[mi][nj], a[mi], b[nj]);
        }
        const int nxt = s + NBUF - 1;
        if (nxt < NSTG) load_stage(nxt, nxt & (NBUF - 1));
        CP_COMMIT();                          // empty group in tail keeps accounting
    }

    // ---- epilogue: += feat, fp32 out
    #pragma unroll
    for (int mi = 0; mi < 2; mi++) {
        const int row0 = m0 + wm0 + mi * 16 + g;
        const int row1 = row0 + 8;
        #pragma unroll
        for (int nj = 0; nj < 4; nj++) {
            const int col = n0 + wn0 + nj * 8 + tg * 2;
            float2 f0 = *(const float2*)(feat + (size_t)row0 * DD + col);
            float2 f1 = *(const float2*)(feat + (size_t)row1 * DD + col);
            float2 o0 = make_float2(c[mi][nj][0] + f0.x, c[mi][nj][1] + f0.y);
            float2 o1 = make_float2(c[mi][nj][2] + f1.x, c[mi][nj][3] + f1.y);
            *(float2*)(out + (size_t)row0 * DD + col) = o0;
            *(float2*)(out + (size_t)row1 * DD + col) = o1;
        }
    }
}

// ================================ host =====================================
#define GEMM_SMEM (NBUF * 2 * 128 * STRD * 2)   // 81920 B

extern "C" void kernel_launch(void* const* d_in, const int* in_sizes, int n_in,
                              void* d_out, int out_size) {
    const float* feat = (const float*)d_in[0];
    const int*   g32  = (const int*)d_in[1];
    const float* w    = (const float*)d_in[2];
    const float* bias = (const float*)d_in[3];
    float* out = (float*)d_out;

    static bool attr_set = false;
    if (!attr_set) {
        cudaFuncSetAttribute(gemm_mma_kernel,
                             cudaFuncAttributeMaxDynamicSharedMemorySize, GEMM_SMEM);
        attr_set = true;
    }

    prepB_kernel<<<DD, 128>>>(w, bias, g32);        // also runs dtype probe once
    prepA_kernel<<<ROWS / 2, 128>>>(feat, g32);
    dim3 grid(DD / 128, ROWS / 128);                // (4, 32) = 128 CTAs
    gemm_mma_kernel<<<grid, 512, GEMM_SMEM>>>(feat, out);
}

// round 11
// speedup vs baseline: 4.2701x; 1.1127x over previous
#include <cuda_runtime.h>
#include <cuda_fp16.h>
#include <cstdint>

#define DD    512
#define ROWS  4096
#define NLAB  16
#define KTOT  576            // 512 feat + 16 counts/bias + 48 zero pad
#define BK    64             // halves per stage
#define NSTG  9              // 576/64
#define STRD  72             // smem row stride in halves (144B, conflict-free, 16B-mult)
#define NBUF  3              // cp.async ring depth

// ---------------- device-global scratch (allocation-free rule) -------------
__device__ __align__(16) __half g_A[ROWS * KTOT];   // 4.7 MB
__device__ __align__(16) __half g_B[DD * KTOT];     // 0.59 MB

// ---------------------------------------------------------------------------
// prep_kernel: grid 2560 x 128 threads.
//  blocks 0..2047  : A path, 2 feat rows each ->
//      g_A[r][0:512]=half(feat), [512+l]=label count, [528:576]=0
//      per-block int64-vs-int32 probe (64 L2-hot samples; labels<16 => odd
//      int32 slots all zero iff int64)
//  blocks 2048..2559: B path, one o-row each ->
//      g_B[o][k]=half(w0+w1) k<512; half(bias[k-512][o]) 512<=k<528; 0 else
// ---------------------------------------------------------------------------
__global__ __launch_bounds__(128) void prep_kernel(const float* __restrict__ feat,
                                                   const int* __restrict__ g32,
                                                   const float* __restrict__ w,
                                                   const float* __restrict__ bias) {
    const int b = blockIdx.x, t = threadIdx.x;
    if (b < 2048) {
        __shared__ int c[2][NLAB];
        __shared__ int anyOdd;
        const int rl = t >> 6;                  // row within block (0/1)
        const int r  = b * 2 + rl;
        const int colg = (t & 63) * 8;
        if (t < 2 * NLAB) c[t >> 4][t & 15] = 0;
        if (t == 0) anyOdd = 0;
        __syncthreads();

        // probe (64 samples, L2-hot after first wave; max idx 129025 < 524288)
        if (t < 64 && g32[2048 * t + 1]) atomicOr(&anyOdd, 1);

        // feat -> half (8 values per thread), overlaps probe latency
        const float4* fp = (const float4*)(feat + (size_t)r * DD + colg);
        float4 v0 = fp[0], v1 = fp[1];
        __half2 h0 = __floats2half2_rn(v0.x, v0.y);
        __half2 h1 = __floats2half2_rn(v0.z, v0.w);
        __half2 h2 = __floats2half2_rn(v1.x, v1.y);
        __half2 h3 = __floats2half2_rn(v1.z, v1.w);
        uint4 pk;
        pk.x = *(uint32_t*)&h0; pk.y = *(uint32_t*)&h1;
        pk.z = *(uint32_t*)&h2; pk.w = *(uint32_t*)&h3;
        *(uint4*)(g_A + (size_t)r * KTOT + colg) = pk;
        __syncthreads();

        const int is64 = (anyOdd == 0);
        int l0, l1;
        const int pair = r * 64 + (t & 63);
        if (is64) {
            longlong2 q = ((const longlong2*)g32)[pair];
            l0 = (int)q.x; l1 = (int)q.y;
        } else {
            int2 q = ((const int2*)g32)[pair];
            l0 = q.x; l1 = q.y;
        }
        atomicAdd(&c[rl][l0 & (NLAB - 1)], 1);
        atomicAdd(&c[rl][l1 & (NLAB - 1)], 1);
        __syncthreads();

        if (t < 32) {                           // counts -> cols 512..527
            int rr = t >> 4, l = t & 15;
            g_A[(size_t)(b * 2 + rr) * KTOT + DD + l] = __float2half_rn((float)c[rr][l]);
        } else if (t < 44) {                    // zeros -> cols 528..575 (uint4)
            int u = t - 32;                     // 0..11
            int rr = u / 6, col = 528 + (u % 6) * 8;
            uint4 z = make_uint4(0, 0, 0, 0);
            *(uint4*)(g_A + (size_t)(b * 2 + rr) * KTOT + col) = z;
        }
    } else {
        const int o = b - 2048;
        if (t < 64) {
            const int k = t * 8;
            const float4* p0 = (const float4*)(w + (size_t)o * DD + k);
            const float4* p1 = (const float4*)(w + (size_t)DD * DD + (size_t)o * DD + k);
            float4 a0 = p0[0], a1 = p0[1], b0 = p1[0], b1 = p1[1];
            __half2 h0 = __floats2half2_rn(a0.x + b0.x, a0.y + b0.y);
            __half2 h1 = __floats2half2_rn(a0.z + b0.z, a0.w + b0.w);
            __half2 h2 = __floats2half2_rn(a1.x + b1.x, a1.y + b1.y);
            __half2 h3 = __floats2half2_rn(a1.z + b1.z, a1.w + b1.w);
            uint4 pk;
            pk.x = *(uint32_t*)&h0; pk.y = *(uint32_t*)&h1;
            pk.z = *(uint32_t*)&h2; pk.w = *(uint32_t*)&h3;
            *(uint4*)(g_B + (size_t)o * KTOT + k) = pk;
        } else {
            const int u = t - 64;               // 0..63 -> k = 512+u
            float v = (u < NLAB) ? bias[u * DD + o] : 0.f;
            g_B[(size_t)o * KTOT + DD + u] = __float2half_rn(v);
        }
    }
}

// ============================ mma GEMM =====================================
__device__ __forceinline__ uint32_t smem_u32(const void* p) {
    uint32_t a;
    asm("{ .reg .u64 t; cvta.to.shared.u64 t, %1; cvt.u32.u64 %0, t; }" : "=r"(a) : "l"(p));
    return a;
}
#define CP_ASYNC16(dst, src) \
    asm volatile("cp.async.cg.shared.global [%0], [%1], 16;" :: "r"(dst), "l"(src) : "memory")
#define CP_COMMIT() asm volatile("cp.async.commit_group;" ::: "memory")
#define CP_WAIT(n)  asm volatile("cp.async.wait_group %0;" :: "n"(n) : "memory")
#define LDM_X4(r0, r1, r2, r3, addr) \
    asm volatile("ldmatrix.sync.aligned.m8n8.x4.shared.b16 {%0,%1,%2,%3}, [%4];" \
        : "=r"(r0), "=r"(r1), "=r"(r2), "=r"(r3) : "r"(addr))
#define MMA16816(c, a, b) \
    asm volatile("mma.sync.aligned.m16n8k16.row.col.f32.f16.f16.f32 " \
        "{%0,%1,%2,%3}, {%4,%5,%6,%7}, {%8,%9}, {%0,%1,%2,%3};" \
        : "+f"((c)[0]), "+f"((c)[1]), "+f"((c)[2]), "+f"((c)[3]) \
        : "r"((a)[0]), "r"((a)[1]), "r"((a)[2]), "r"((a)[3]), "r"((b)[0]), "r"((b)[1]))

// out[m][n] = sum_k A[m][k]*B[n][k] + feat[m][n]
// 128x128 CTA tile, 512 threads = 16 warps (4x4), warp tile 32x32.
// BK=64 halves/stage (9 stages), 3-deep cp.async ring.
// B tile is [n][k] K-major => NON-trans ldmatrix yields the mma B fragment.
__global__ __launch_bounds__(512) void gemm_mma_kernel(const float* __restrict__ feat,
                                                       float* __restrict__ out) {
    extern __shared__ __align__(16) __half smem[];
    __half* sA = smem;                        // NBUF x 128*STRD
    __half* sB = smem + NBUF * 128 * STRD;    // NBUF x 128*STRD

    const int tid = threadIdx.x, wid = tid >> 5, lane = tid & 31;
    const int g = lane >> 2, tg = lane & 3;
    const int wm0 = (wid >> 2) * 32;          // warp row origin in tile
    const int wn0 = (wid & 3) * 32;           // warp col origin in tile
    const int m0 = blockIdx.y * 128, n0 = blockIdx.x * 128;

    const uint32_t aBase = smem_u32(sA);
    const uint32_t bBase = smem_u32(sB);

    float c[2][4][4];
    #pragma unroll
    for (int i = 0; i < 2; i++)
        #pragma unroll
        for (int j = 0; j < 4; j++)
            #pragma unroll
            for (int q = 0; q < 4; q++) c[i][j][q] = 0.f;

    auto load_stage = [&](int s, int buf) {
        const uint32_t aD = aBase + buf * (128 * STRD * 2);
        const uint32_t bD = bBase + buf * (128 * STRD * 2);
        #pragma unroll
        for (int q = 0; q < 2; q++) {         // 1024 chunks of 8 halves per tile
            const int id = tid + 512 * q;
            const int row = id >> 3, kc = id & 7;
            CP_ASYNC16(aD + (row * STRD + kc * 8) * 2,
                       g_A + (size_t)(m0 + row) * KTOT + s * BK + kc * 8);
            CP_ASYNC16(bD + (row * STRD + kc * 8) * 2,
                       g_B + (size_t)(n0 + row) * KTOT + s * BK + kc * 8);
        }
    };

    #pragma unroll
    for (int i = 0; i < NBUF - 1; i++) { load_stage(i, i); CP_COMMIT(); }

    const int lrow = lane & 15, lcol8 = (lane >> 4) << 3;

    for (int s = 0; s < NSTG; s++) {
        const int buf = s % NBUF;
        CP_WAIT(NBUF - 2);                    // stage s resident
        __syncthreads();                      // publish; also fences buf reuse
        const uint32_t aT = aBase + buf * (128 * STRD * 2);
        const uint32_t bT = bBase + buf * (128 * STRD * 2);
        #pragma unroll
        for (int ks = 0; ks < 4; ks++) {      // four k16 steps per stage
            uint32_t a[2][4], b[4][2];
            #pragma unroll
            for (int mi = 0; mi < 2; mi++) {
                uint32_t addr = aT + ((wm0 + mi * 16 + lrow) * STRD + ks * 16 + lcol8) * 2;
                LDM_X4(a[mi][0], a[mi][1], a[mi][2], a[mi][3], addr);
            }
            #pragma unroll
            for (int nb = 0; nb < 2; nb++) {  // each x4 covers 2 n-frags (16 n)
                uint32_t t0, t1, t2, t3;
                uint32_t addr = bT + ((wn0 + nb * 16 + lrow) * STRD + ks * 16 + lcol8) * 2;
                LDM_X4(t0, t1, t2, t3, addr);
                b[2 * nb][0] = t0; b[2 * nb + 1][0] = t1;
                b[2 * nb][1] = t2; b[2 * nb + 1][1] = t3;
            }
            #pragma unroll
            for (int mi = 0; mi < 2; mi++)
                #pragma unroll
                for (int nj = 0; nj < 4; nj++)
                    MMA16816(c[mi][nj], a[mi], b[nj]);
        }
        const int nxt = s + NBUF - 1;
        if (nxt < NSTG) load_stage(nxt, nxt % NBUF);
        CP_COMMIT();                          // empty group in tail keeps accounting
    }

    // ---- epilogue: += feat, fp32 out
    #pragma unroll
    for (int mi = 0; mi < 2; mi++) {
        const int row0 = m0 + wm0 + mi * 16 + g;
        const int row1 = row0 + 8;
        #pragma unroll
        for (int nj = 0; nj < 4; nj++) {
            const int col = n0 + wn0 + nj * 8 + tg * 2;
            float2 f0 = *(const float2*)(feat + (size_t)row0 * DD + col);
            float2 f1 = *(const float2*)(feat + (size_t)row1 * DD + col);
            float2 o0 = make_float2(c[mi][nj][0] + f0.x, c[mi][nj][1] + f0.y);
            float2 o1 = make_float2(c[mi][nj][2] + f1.x, c[mi][nj][3] + f1.y);
            *(float2*)(out + (size_t)row0 * DD + col) = o0;
            *(float2*)(out + (size_t)row1 * DD + col) = o1;
        }
    }
}

// ================================ host =====================================
#define GEMM_SMEM (NBUF * 2 * 128 * STRD * 2)   // 110592 B

extern "C" void kernel_launch(void* const* d_in, const int* in_sizes, int n_in,
                              void* d_out, int out_size) {
    const float* feat = (const float*)d_in[0];
    const int*   g32  = (const int*)d_in[1];
    const float* w    = (const float*)d_in[2];
    const float* bias = (const float*)d_in[3];
    float* out = (float*)d_out;

    static bool attr_set = false;
    if (!attr_set) {
        cudaFuncSetAttribute(gemm_mma_kernel,
                             cudaFuncAttributeMaxDynamicSharedMemorySize, GEMM_SMEM);
        attr_set = true;
    }

    prep_kernel<<<2560, 128>>>(feat, g32, w, bias);
    dim3 grid(DD / 128, ROWS / 128);                // (4, 32) = 128 CTAs
    gemm_mma_kernel<<<grid, 512, GEMM_SMEM>>>(feat, out);
}

// round 12
// speedup vs baseline: 4.3234x; 1.0125x over previous
#include <cuda_runtime.h>
#include <cuda_fp16.h>
#include <cstdint>

#define DD    512
#define ROWS  4096
#define NLAB  16
#define KTOT  576            // 512 feat + 16 counts/bias + 48 zero pad
#define BK    64             // halves per stage
#define NSTG  9              // 576/64
#define NBUF  3              // bulk-copy ring depth
#define BLKH  8192           // halves per 128x64 stage block (16 KB)
#define BLKB  16384          // bytes per stage block

// Tiled scratch: g_A = [m_tile(32)][stage(9)][128 rows x 64 halves, swizzled]
//                g_B = [n_tile(4) ][stage(9)][128 rows x 64 halves, swizzled]
// Swizzle: within a block, row r / half-col k -> byte (r*128 + k*2) ^ ((r&7)<<4)
__device__ __align__(16) __half g_A[ROWS / 128 * NSTG * BLKH];   // 4.7 MB
__device__ __align__(16) __half g_B[DD / 128 * NSTG * BLKH];     // 0.59 MB

__device__ __forceinline__ uint32_t swz(int row, int byteInRow) {
    return (uint32_t)((row * 128 + byteInRow) ^ ((row & 7) << 4));
}

// ---------------------------------------------------------------------------
// prep_kernel: grid 2560 x 128 threads.
//  blocks 0..2047  : A path, 2 feat rows each (feat->half, label counts, pad)
//  blocks 2048..2559: B path, one o-row each (w0+w1, bias^T, pad)
// ---------------------------------------------------------------------------
__global__ __launch_bounds__(128) void prep_kernel(const float* __restrict__ feat,
                                                   const int* __restrict__ g32,
                                                   const float* __restrict__ w,
                                                   const float* __restrict__ bias) {
    const int b = blockIdx.x, t = threadIdx.x;
    char* const gA = (char*)g_A;
    char* const gB = (char*)g_B;
    if (b < 2048) {
        __shared__ int c[2][NLAB];
        __shared__ int anyOdd;
        const int rl = t >> 6;                  // row within block (0/1)
        const int r  = b * 2 + rl;
        const int colg = (t & 63) * 8;          // half col 0..504, mult of 8
        if (t < 2 * NLAB) c[t >> 4][t & 15] = 0;
        if (t == 0) anyOdd = 0;
        __syncthreads();

        // int64-vs-int32 probe (labels<16 => odd int32 slots all zero iff i64)
        if (t < 64 && g32[2048 * t + 1]) atomicOr(&anyOdd, 1);

        const float4* fp = (const float4*)(feat + (size_t)r * DD + colg);
        float4 v0 = fp[0], v1 = fp[1];
        __half2 h0 = __floats2half2_rn(v0.x, v0.y);
        __half2 h1 = __floats2half2_rn(v0.z, v0.w);
        __half2 h2 = __floats2half2_rn(v1.x, v1.y);
        __half2 h3 = __floats2half2_rn(v1.z, v1.w);
        uint4 pk;
        pk.x = *(uint32_t*)&h0; pk.y = *(uint32_t*)&h1;
        pk.z = *(uint32_t*)&h2; pk.w = *(uint32_t*)&h3;
        {
            const int stage = colg >> 6, kin = colg & 63, rr = r & 127;
            size_t base = (size_t)((r >> 7) * NSTG + stage) * BLKB;
            *(uint4*)(gA + base + swz(rr, kin * 2)) = pk;
        }
        __syncthreads();

        const int is64 = (anyOdd == 0);
        int l0, l1;
        const int pair = r * 64 + (t & 63);
        if (is64) {
            longlong2 q = ((const longlong2*)g32)[pair];
            l0 = (int)q.x; l1 = (int)q.y;
        } else {
            int2 q = ((const int2*)g32)[pair];
            l0 = q.x; l1 = q.y;
        }
        atomicAdd(&c[rl][l0 & (NLAB - 1)], 1);
        atomicAdd(&c[rl][l1 & (NLAB - 1)], 1);
        __syncthreads();

        // stage-8 block: counts at kin 0..15, zeros kin 16..63
        if (t < 32) {
            int rr2 = t >> 4, l = t & 15;
            int r2 = b * 2 + rr2, rr = r2 & 127;
            size_t base = (size_t)((r2 >> 7) * NSTG + 8) * BLKB;
            *(__half*)(gA + base + swz(rr, l * 2)) = __float2half_rn((float)c[rr2][l]);
        } else if (t < 44) {
            int u = t - 32;                     // 0..11
            int rr2 = u / 6, j = u % 6;         // 6 x 16B chunks: bytes 32..127
            int r2 = b * 2 + rr2, rr = r2 & 127;
            size_t base = (size_t)((r2 >> 7) * NSTG + 8) * BLKB;
            *(uint4*)(gA + base + swz(rr, 32 + j * 16)) = make_uint4(0, 0, 0, 0);
        }
    } else {
        const int o = b - 2048, oo = o & 127;
        if (t < 64) {
            const int k = t * 8;
            const float4* p0 = (const float4*)(w + (size_t)o * DD + k);
            const float4* p1 = (const float4*)(w + (size_t)DD * DD + (size_t)o * DD + k);
            float4 a0 = p0[0], a1 = p0[1], b0 = p1[0], b1 = p1[1];
            __half2 h0 = __floats2half2_rn(a0.x + b0.x, a0.y + b0.y);
            __half2 h1 = __floats2half2_rn(a0.z + b0.z, a0.w + b0.w);
            __half2 h2 = __floats2half2_rn(a1.x + b1.x, a1.y + b1.y);
            __half2 h3 = __floats2half2_rn(a1.z + b1.z, a1.w + b1.w);
            uint4 pk;
            pk.x = *(uint32_t*)&h0; pk.y = *(uint32_t*)&h1;
            pk.z = *(uint32_t*)&h2; pk.w = *(uint32_t*)&h3;
            size_t base = (size_t)((o >> 7) * NSTG + (k >> 6)) * BLKB;
            *(uint4*)(gB + base + swz(oo, (k & 63) * 2)) = pk;
        } else {
            const int u = t - 64;               // 0..63 -> stage 8, kin u
            float v = (u < NLAB) ? bias[u * DD + o] : 0.f;
            size_t base = (size_t)((o >> 7) * NSTG + 8) * BLKB;
            *(__half*)(gB + base + swz(oo, u * 2)) = __float2half_rn(v);
        }
    }
}

// ============================ mma GEMM =====================================
__device__ __forceinline__ uint32_t smem_u32(const void* p) {
    uint32_t a;
    asm("{ .reg .u64 t; cvta.to.shared.u64 t, %1; cvt.u32.u64 %0, t; }" : "=r"(a) : "l"(p));
    return a;
}
#define MBAR_INIT(addr, cnt) \
    asm volatile("mbarrier.init.shared.b64 [%0], %1;" :: "r"(addr), "r"((uint32_t)(cnt)) : "memory")
#define MBAR_EXPECT_TX(addr, bytes) \
    asm volatile("mbarrier.arrive.expect_tx.shared.b64 _, [%0], %1;" :: "r"(addr), "r"((uint32_t)(bytes)) : "memory")
#define MBAR_WAIT(addr, par) do {                                            \
    asm volatile("{\n\t.reg .pred P;\n\tWL_%=:\n\t"                           \
        "mbarrier.try_wait.parity.acquire.cta.shared::cta.b64 P, [%0], %1, 0x989680;\n\t" \
        "@P bra.uni WD_%=;\n\tbra.uni WL_%=;\n\tWD_%=:\n\t}"                  \
        :: "r"(addr), "r"((uint32_t)(par)) : "memory"); } while (0)
#define BULK_G2S(dst, src, bytes, mbar) \
    asm volatile("cp.async.bulk.shared::cluster.global.mbarrier::complete_tx::bytes " \
        "[%0], [%1], %2, [%3];" \
        :: "r"(dst), "l"(src), "r"((uint32_t)(bytes)), "r"(mbar) : "memory")
#define LDM_X4(r0, r1, r2, r3, addr) \
    asm volatile("ldmatrix.sync.aligned.m8n8.x4.shared.b16 {%0,%1,%2,%3}, [%4];" \
        : "=r"(r0), "=r"(r1), "=r"(r2), "=r"(r3) : "r"(addr))
#define MMA16816(c, a, b) \
    asm volatile("mma.sync.aligned.m16n8k16.row.col.f32.f16.f16.f32 " \
        "{%0,%1,%2,%3}, {%4,%5,%6,%7}, {%8,%9}, {%0,%1,%2,%3};" \
        : "+f"((c)[0]), "+f"((c)[1]), "+f"((c)[2]), "+f"((c)[3]) \
        : "r"((a)[0]), "r"((a)[1]), "r"((a)[2]), "r"((a)[3]), "r"((b)[0]), "r"((b)[1]))

// smem: [0:64) mbarriers (3 x 8B), data at 1024: buf i = A 16K + B 16K
#define SM_DATA  1024
#define BUFBYTES (2 * BLKB)
#define GEMM_SMEM (SM_DATA + NBUF * BUFBYTES)   // 99328 B

// out[m][n] = sum_k A[m][k]*B[n][k] + feat[m][n]
// 128x128 CTA tile, 512 threads = 16 warps (4x4), warp tile 32x32.
// Stage data arrives via cp.async.bulk (one producer thread, mbarrier tx).
__global__ __launch_bounds__(512) void gemm_mma_kernel(const float* __restrict__ feat,
                                                       float* __restrict__ out) {
    extern __shared__ __align__(16) char smem[];
    const uint32_t sb = smem_u32(smem);

    const int tid = threadIdx.x, wid = tid >> 5, lane = tid & 31;
    const int g = lane >> 2, tg = lane & 3;
    const int wm0 = (wid >> 2) * 32;          // warp row origin in tile
    const int wn0 = (wid & 3) * 32;           // warp col origin in tile
    const int mt = blockIdx.y, nt = blockIdx.x;
    const int m0 = mt * 128, n0 = nt * 128;
    const char* const gA = (const char*)g_A;
    const char* const gB = (const char*)g_B;

    if (tid == 0) {
        #pragma unroll
        for (int i = 0; i < NBUF; i++) MBAR_INIT(sb + 8 * i, 1);
    }
    __syncthreads();

    auto load_stage = [&](int s, int buf) {   // tid0 only
        const uint32_t mb = sb + 8 * buf;
        const uint32_t dst = sb + SM_DATA + buf * BUFBYTES;
        MBAR_EXPECT_TX(mb, BUFBYTES);
        BULK_G2S(dst,        gA + (size_t)(mt * NSTG + s) * BLKB, BLKB, mb);
        BULK_G2S(dst + BLKB, gB + (size_t)(nt * NSTG + s) * BLKB, BLKB, mb);
    };
    if (tid == 0) { load_stage(0, 0); load_stage(1, 1); }

    float c[2][4][4];
    #pragma unroll
    for (int i = 0; i < 2; i++)
        #pragma unroll
        for (int j = 0; j < 4; j++)
            #pragma unroll
            for (int q = 0; q < 4; q++) c[i][j][q] = 0.f;

    const int lrow = lane & 15;
    const int lcolB = ((lane >> 4) << 3) * 2;     // byte offset {0,16} within k16

    for (int s = 0; s < NSTG; s++) {
        const int buf = s % NBUF;
        MBAR_WAIT(sb + 8 * buf, (s / NBUF) & 1);
        const uint32_t aT = sb + SM_DATA + buf * BUFBYTES;
        const uint32_t bT = aT + BLKB;
        #pragma unroll
        for (int ks = 0; ks < 4; ks++) {      // four k16 steps per stage
            uint32_t a[2][4], b[4][2];
            #pragma unroll
            for (int mi = 0; mi < 2; mi++) {
                const int row = wm0 + mi * 16 + lrow;
                LDM_X4(a[mi][0], a[mi][1], a[mi][2], a[mi][3],
                       aT + swz(row, ks * 32 + lcolB));
            }
            #pragma unroll
            for (int nb = 0; nb < 2; nb++) {
                const int row = wn0 + nb * 16 + lrow;
                uint32_t t0, t1, t2, t3;
                LDM_X4(t0, t1, t2, t3, bT + swz(row, ks * 32 + lcolB));
                b[2 * nb][0] = t0; b[2 * nb + 1][0] = t1;
                b[2 * nb][1] = t2; b[2 * nb + 1][1] = t3;
            }
            #pragma unroll
            for (int mi = 0; mi < 2; mi++)
                #pragma unroll
                for (int nj = 0; nj < 4; nj++)
                    MMA16816(c[mi][nj], a[mi], b[nj]);
        }
        __syncthreads();                      // all reads of buf (s-1 ring) done
        if (tid == 0 && s + NBUF - 1 < NSTG)
            load_stage(s + NBUF - 1, (s + NBUF - 1) % NBUF);
    }

    // ---- epilogue: += feat, fp32 out
    #pragma unroll
    for (int mi = 0; mi < 2; mi++) {
        const int row0 = m0 + wm0 + mi * 16 + g;
        const int row1 = row0 + 8;
        #pragma unroll
        for (int nj = 0; nj < 4; nj++) {
            const int col = n0 + wn0 + nj * 8 + tg * 2;
            float2 f0 = *(const float2*)(feat + (size_t)row0 * DD + col);
            float2 f1 = *(const float2*)(feat + (size_t)row1 * DD + col);
            float2 o0 = make_float2(c[mi][nj][0] + f0.x, c[mi][nj][1] + f0.y);
            float2 o1 = make_float2(c[mi][nj][2] + f1.x, c[mi][nj][3] + f1.y);
            *(float2*)(out + (size_t)row0 * DD + col) = o0;
            *(float2*)(out + (size_t)row1 * DD + col) = o1;
        }
    }
}

// ================================ host =====================================
extern "C" void kernel_launch(void* const* d_in, const int* in_sizes, int n_in,
                              void* d_out, int out_size) {
    const float* feat = (const float*)d_in[0];
    const int*   g32  = (const int*)d_in[1];
    const float* w    = (const float*)d_in[2];
    const float* bias = (const float*)d_in[3];
    float* out = (float*)d_out;

    static bool attr_set = false;
    if (!attr_set) {
        cudaFuncSetAttribute(gemm_mma_kernel,
                             cudaFuncAttributeMaxDynamicSharedMemorySize, GEMM_SMEM);
        attr_set = true;
    }

    prep_kernel<<<2560, 128>>>(feat, g32, w, bias);
    dim3 grid(DD / 128, ROWS / 128);                // (4, 32) = 128 CTAs
    gemm_mma_kernel<<<grid, 512, GEMM_SMEM>>>(feat, out);
}

// round 13
// speedup vs baseline: 4.3575x; 1.0079x over previous
#include <cuda_runtime.h>
#include <cuda_fp16.h>
#include <cstdint>

#define DD    512
#define ROWS  4096
#define NLAB  16
#define KTOT  576            // 512 feat + 16 counts/bias + 48 zero pad
#define BK    64             // halves per stage
#define NSTG  9              // 576/64
#define NBUF  6              // bulk-copy ring depth (deep: hide full load latency)
#define BLKH  8192           // halves per 128x64 stage block (16 KB)
#define BLKB  16384          // bytes per stage block

// Tiled scratch: g_A = [m_tile(32)][stage(9)][128 rows x 64 halves, swizzled]
//                g_B = [n_tile(4) ][stage(9)][128 rows x 64 halves, swizzled]
// Swizzle: within a block, row r / half-col k -> byte (r*128 + k*2) ^ ((r&7)<<4)
__device__ __align__(16) __half g_A[ROWS / 128 * NSTG * BLKH];   // 4.7 MB
__device__ __align__(16) __half g_B[DD / 128 * NSTG * BLKH];     // 0.59 MB

__device__ __forceinline__ uint32_t swz(int row, int byteInRow) {
    return (uint32_t)((row * 128 + byteInRow) ^ ((row & 7) << 4));
}

// ---------------------------------------------------------------------------
// prep_kernel: grid 2560 x 128 threads.
//  blocks 0..2047  : A path, 2 feat rows each (feat->half, label counts, pad)
//  blocks 2048..2559: B path, one o-row each (w0+w1, bias^T, pad)
// ---------------------------------------------------------------------------
__global__ __launch_bounds__(128) void prep_kernel(const float* __restrict__ feat,
                                                   const int* __restrict__ g32,
                                                   const float* __restrict__ w,
                                                   const float* __restrict__ bias) {
    const int b = blockIdx.x, t = threadIdx.x;
    char* const gA = (char*)g_A;
    char* const gB = (char*)g_B;
    if (b < 2048) {
        __shared__ int c[2][NLAB];
        __shared__ int anyOdd;
        const int rl = t >> 6;                  // row within block (0/1)
        const int r  = b * 2 + rl;
        const int colg = (t & 63) * 8;          // half col 0..504, mult of 8
        if (t < 2 * NLAB) c[t >> 4][t & 15] = 0;
        if (t == 0) anyOdd = 0;
        __syncthreads();

        // int64-vs-int32 probe (labels<16 => odd int32 slots all zero iff i64)
        if (t < 64 && g32[2048 * t + 1]) atomicOr(&anyOdd, 1);

        const float4* fp = (const float4*)(feat + (size_t)r * DD + colg);
        float4 v0 = fp[0], v1 = fp[1];
        __half2 h0 = __floats2half2_rn(v0.x, v0.y);
        __half2 h1 = __floats2half2_rn(v0.z, v0.w);
        __half2 h2 = __floats2half2_rn(v1.x, v1.y);
        __half2 h3 = __floats2half2_rn(v1.z, v1.w);
        uint4 pk;
        pk.x = *(uint32_t*)&h0; pk.y = *(uint32_t*)&h1;
        pk.z = *(uint32_t*)&h2; pk.w = *(uint32_t*)&h3;
        {
            const int stage = colg >> 6, kin = colg & 63, rr = r & 127;
            size_t base = (size_t)((r >> 7) * NSTG + stage) * BLKB;
            *(uint4*)(gA + base + swz(rr, kin * 2)) = pk;
        }
        __syncthreads();

        const int is64 = (anyOdd == 0);
        int l0, l1;
        const int pair = r * 64 + (t & 63);
        if (is64) {
            longlong2 q = ((const longlong2*)g32)[pair];
            l0 = (int)q.x; l1 = (int)q.y;
        } else {
            int2 q = ((const int2*)g32)[pair];
            l0 = q.x; l1 = q.y;
        }
        atomicAdd(&c[rl][l0 & (NLAB - 1)], 1);
        atomicAdd(&c[rl][l1 & (NLAB - 1)], 1);
        __syncthreads();

        // stage-8 block: counts at kin 0..15, zeros kin 16..63
        if (t < 32) {
            int rr2 = t >> 4, l = t & 15;
            int r2 = b * 2 + rr2, rr = r2 & 127;
            size_t base = (size_t)((r2 >> 7) * NSTG + 8) * BLKB;
            *(__half*)(gA + base + swz(rr, l * 2)) = __float2half_rn((float)c[rr2][l]);
        } else if (t < 44) {
            int u = t - 32;                     // 0..11
            int rr2 = u / 6, j = u % 6;         // 6 x 16B chunks: bytes 32..127
            int r2 = b * 2 + rr2, rr = r2 & 127;
            size_t base = (size_t)((r2 >> 7) * NSTG + 8) * BLKB;
            *(uint4*)(gA + base + swz(rr, 32 + j * 16)) = make_uint4(0, 0, 0, 0);
        }
    } else {
        const int o = b - 2048, oo = o & 127;
        if (t < 64) {
            const int k = t * 8;
            const float4* p0 = (const float4*)(w + (size_t)o * DD + k);
            const float4* p1 = (const float4*)(w + (size_t)DD * DD + (size_t)o * DD + k);
            float4 a0 = p0[0], a1 = p0[1], b0 = p1[0], b1 = p1[1];
            __half2 h0 = __floats2half2_rn(a0.x + b0.x, a0.y + b0.y);
            __half2 h1 = __floats2half2_rn(a0.z + b0.z, a0.w + b0.w);
            __half2 h2 = __floats2half2_rn(a1.x + b1.x, a1.y + b1.y);
            __half2 h3 = __floats2half2_rn(a1.z + b1.z, a1.w + b1.w);
            uint4 pk;
            pk.x = *(uint32_t*)&h0; pk.y = *(uint32_t*)&h1;
            pk.z = *(uint32_t*)&h2; pk.w = *(uint32_t*)&h3;
            size_t base = (size_t)((o >> 7) * NSTG + (k >> 6)) * BLKB;
            *(uint4*)(gB + base + swz(oo, (k & 63) * 2)) = pk;
        } else {
            const int u = t - 64;               // 0..63 -> stage 8, kin u
            float v = (u < NLAB) ? bias[u * DD + o] : 0.f;
            size_t base = (size_t)((o >> 7) * NSTG + 8) * BLKB;
            *(__half*)(gB + base + swz(oo, u * 2)) = __float2half_rn(v);
        }
    }
}

// ============================ mma GEMM =====================================
__device__ __forceinline__ uint32_t smem_u32(const void* p) {
    uint32_t a;
    asm("{ .reg .u64 t; cvta.to.shared.u64 t, %1; cvt.u32.u64 %0, t; }" : "=r"(a) : "l"(p));
    return a;
}
#define MBAR_INIT(addr, cnt) \
    asm volatile("mbarrier.init.shared.b64 [%0], %1;" :: "r"(addr), "r"((uint32_t)(cnt)) : "memory")
#define MBAR_EXPECT_TX(addr, bytes) \
    asm volatile("mbarrier.arrive.expect_tx.shared.b64 _, [%0], %1;" :: "r"(addr), "r"((uint32_t)(bytes)) : "memory")
#define MBAR_WAIT(addr, par) do {                                            \
    asm volatile("{\n\t.reg .pred P;\n\tWL_%=:\n\t"                           \
        "mbarrier.try_wait.parity.acquire.cta.shared::cta.b64 P, [%0], %1, 0x989680;\n\t" \
        "@P bra.uni WD_%=;\n\tbra.uni WL_%=;\n\tWD_%=:\n\t}"                  \
        :: "r"(addr), "r"((uint32_t)(par)) : "memory"); } while (0)
#define BULK_G2S(dst, src, bytes, mbar) \
    asm volatile("cp.async.bulk.shared::cluster.global.mbarrier::complete_tx::bytes " \
        "[%0], [%1], %2, [%3];" \
        :: "r"(dst), "l"(src), "r"((uint32_t)(bytes)), "r"(mbar) : "memory")
#define LDM_X4(r0, r1, r2, r3, addr) \
    asm volatile("ldmatrix.sync.aligned.m8n8.x4.shared.b16 {%0,%1,%2,%3}, [%4];" \
        : "=r"(r0), "=r"(r1), "=r"(r2), "=r"(r3) : "r"(addr))
#define MMA16816(c, a, b) \
    asm volatile("mma.sync.aligned.m16n8k16.row.col.f32.f16.f16.f32 " \
        "{%0,%1,%2,%3}, {%4,%5,%6,%7}, {%8,%9}, {%0,%1,%2,%3};" \
        : "+f"((c)[0]), "+f"((c)[1]), "+f"((c)[2]), "+f"((c)[3]) \
        : "r"((a)[0]), "r"((a)[1]), "r"((a)[2]), "r"((a)[3]), "r"((b)[0]), "r"((b)[1]))

// smem: [0:64) mbarriers (6 x 8B), data at 1024: buf i = A 16K + B 16K
#define SM_DATA  1024
#define BUFBYTES (2 * BLKB)
#define GEMM_SMEM (SM_DATA + NBUF * BUFBYTES)   // 197632 B

// out[m][n] = sum_k A[m][k]*B[n][k] + feat[m][n]
// 128x128 CTA tile, 512 threads = 16 warps (4x4), warp tile 32x32.
// 6-deep cp.async.bulk ring: loads issued 5 stages ahead -> latency hidden.
__global__ __launch_bounds__(512) void gemm_mma_kernel(const float* __restrict__ feat,
                                                       float* __restrict__ out) {
    extern __shared__ __align__(16) char smem[];
    const uint32_t sb = smem_u32(smem);

    const int tid = threadIdx.x, wid = tid >> 5, lane = tid & 31;
    const int g = lane >> 2, tg = lane & 3;
    const int wm0 = (wid >> 2) * 32;          // warp row origin in tile
    const int wn0 = (wid & 3) * 32;           // warp col origin in tile
    const int mt = blockIdx.y, nt = blockIdx.x;
    const int m0 = mt * 128, n0 = nt * 128;
    const char* const gA = (const char*)g_A;
    const char* const gB = (const char*)g_B;

    if (tid == 0) {
        #pragma unroll
        for (int i = 0; i < NBUF; i++) MBAR_INIT(sb + 8 * i, 1);
    }
    __syncthreads();

    auto load_stage = [&](int s, int buf) {   // tid0 only
        const uint32_t mb = sb + 8 * buf;
        const uint32_t dst = sb + SM_DATA + buf * BUFBYTES;
        MBAR_EXPECT_TX(mb, BUFBYTES);
        BULK_G2S(dst,        gA + (size_t)(mt * NSTG + s) * BLKB, BLKB, mb);
        BULK_G2S(dst + BLKB, gB + (size_t)(nt * NSTG + s) * BLKB, BLKB, mb);
    };
    if (tid == 0) {
        #pragma unroll
        for (int i = 0; i < NBUF - 1; i++) load_stage(i, i);
    }

    // Prefetch epilogue feat operands (latency amortized over the mainloop)
    float2 fpre[2][4][2];
    #pragma unroll
    for (int mi = 0; mi < 2; mi++) {
        const int row0 = m0 + wm0 + mi * 16 + g;
        #pragma unroll
        for (int nj = 0; nj < 4; nj++) {
            const int col = n0 + wn0 + nj * 8 + tg * 2;
            fpre[mi][nj][0] = *(const float2*)(feat + (size_t)row0 * DD + col);
            fpre[mi][nj][1] = *(const float2*)(feat + (size_t)(row0 + 8) * DD + col);
        }
    }

    float c[2][4][4];
    #pragma unroll
    for (int i = 0; i < 2; i++)
        #pragma unroll
        for (int j = 0; j < 4; j++)
            #pragma unroll
            for (int q = 0; q < 4; q++) c[i][j][q] = 0.f;

    const int lrow = lane & 15;
    const int lcolB = ((lane >> 4) << 3) * 2;     // byte offset {0,16} within k16

    for (int s = 0; s < NSTG; s++) {
        const int buf = s % NBUF;
        MBAR_WAIT(sb + 8 * buf, (s / NBUF) & 1);
        const uint32_t aT = sb + SM_DATA + buf * BUFBYTES;
        const uint32_t bT = aT + BLKB;
        #pragma unroll
        for (int ks = 0; ks < 4; ks++) {      // four k16 steps per stage
            uint32_t a[2][4], b[4][2];
            #pragma unroll
            for (int mi = 0; mi < 2; mi++) {
                const int row = wm0 + mi * 16 + lrow;
                LDM_X4(a[mi][0], a[mi][1], a[mi][2], a[mi][3],
                       aT + swz(row, ks * 32 + lcolB));
            }
            #pragma unroll
            for (int nb = 0; nb < 2; nb++) {
                const int row = wn0 + nb * 16 + lrow;
                uint32_t t0, t1, t2, t3;
                LDM_X4(t0, t1, t2, t3, bT + swz(row, ks * 32 + lcolB));
                b[2 * nb][0] = t0; b[2 * nb + 1][0] = t1;
                b[2 * nb][1] = t2; b[2 * nb + 1][1] = t3;
            }
            #pragma unroll
            for (int mi = 0; mi < 2; mi++)
                #pragma unroll
                for (int nj = 0; nj < 4; nj++)
                    MMA16816(c[mi][nj], a[mi], b[nj]);
        }
        __syncthreads();                      // all reads of buf (ring reuse) done
        if (tid == 0 && s + NBUF - 1 < NSTG)
            load_stage(s + NBUF - 1, (s + NBUF - 1) % NBUF);
    }

    // ---- epilogue: += prefetched feat, fp32 out
    #pragma unroll
    for (int mi = 0; mi < 2; mi++) {
        const int row0 = m0 + wm0 + mi * 16 + g;
        const int row1 = row0 + 8;
        #pragma unroll
        for (int nj = 0; nj < 4; nj++) {
            const int col = n0 + wn0 + nj * 8 + tg * 2;
            float2 f0 = fpre[mi][nj][0], f1 = fpre[mi][nj][1];
            float2 o0 = make_float2(c[mi][nj][0] + f0.x, c[mi][nj][1] + f0.y);
            float2 o1 = make_float2(c[mi][nj][2] + f1.x, c[mi][nj][3] + f1.y);
            *(float2*)(out + (size_t)row0 * DD + col) = o0;
            *(float2*)(out + (size_t)row1 * DD + col) = o1;
        }
    }
}

// ================================ host =====================================
extern "C" void kernel_launch(void* const* d_in, const int* in_sizes, int n_in,
                              void* d_out, int out_size) {
    const float* feat = (const float*)d_in[0];
    const int*   g32  = (const int*)d_in[1];
    const float* w    = (const float*)d_in[2];
    const float* bias = (const float*)d_in[3];
    float* out = (float*)d_out;

    static bool attr_set = false;
    if (!attr_set) {
        cudaFuncSetAttribute(gemm_mma_kernel,
                             cudaFuncAttributeMaxDynamicSharedMemorySize, GEMM_SMEM);
        attr_set = true;
    }

    prep_kernel<<<2560, 128>>>(feat, g32, w, bias);
    dim3 grid(DD / 128, ROWS / 128);                // (4, 32) = 128 CTAs
    gemm_mma_kernel<<<grid, 512, GEMM_SMEM>>>(feat, out);
}